// round 15
// baseline (speedup 1.0000x reference)
#include <cuda_runtime.h>

// Problem shape (fixed by dataset): x [512,1024] f32, a,b [1024,64,1] f32, a0 [1] f32
// out [512,1024] f32.
#define BATCH 512
#define NP    1024
#define NK    64

typedef unsigned long long u64;

// Scratch for the pa/pb GEMM results (device globals: allocation-free rule).
__device__ float g_pa[BATCH * NK];
__device__ float g_pb[BATCH * NK];

// ---------- packed f32x2 helpers (sm_103a FFMA2 path, PTX-only) ----------
__device__ __forceinline__ u64 ffma2(u64 a, u64 b, u64 c) {
    u64 d;
    asm("fma.rn.f32x2 %0, %1, %2, %3;" : "=l"(d) : "l"(a), "l"(b), "l"(c));
    return d;
}
__device__ __forceinline__ u64 fadd2(u64 a, u64 b) {
    u64 d;
    asm("add.rn.f32x2 %0, %1, %2;" : "=l"(d) : "l"(a), "l"(b));
    return d;
}
__device__ __forceinline__ u64 pack2(float lo, float hi) {
    u64 d;
    asm("mov.b64 %0, {%1, %2};"
        : "=l"(d) : "r"(__float_as_uint(lo)), "r"(__float_as_uint(hi)));
    return d;
}
__device__ __forceinline__ float2 unpack2(u64 v) {
    unsigned lo, hi;
    asm("mov.b64 {%0, %1}, %2;" : "=r"(lo), "=r"(hi) : "l"(v));
    return make_float2(__uint_as_float(lo), __uint_as_float(hi));
}

// ============================================================================
// Kernel 1 (NEW 16-row tiles): pa[b,k] = sum_p x[b,p]*a[p,k]; pb likewise.
// Grid = 32 b-tiles (16 rows) x 4 k-tiles = 128 blocks, 512 threads.
// Halves a/b L2 traffic vs the 8-row version (32MB -> 16MB; total 24MB) with
// identical per-loaded-SM FFMA2 work.
// x staged as floats, row stride 1026 (float2-aligned; rows 4 apart -> banks
// {0,8,16,24}: conflict-free 4-row LDS at fixed p).
// Thread map: kq = tid&3 (k-quad), rg = (tid>>2)&3 (4 rows each),
// pg = tid>>4 (32 p-groups). Inner loop per p:
//   2x LDG.128 (a,b quad) + 4x LDS.32 + 4x pack + 16 FFMA2.
// ============================================================================
#define SXF_STRIDE 1026   // floats; see bank analysis above

__global__ __launch_bounds__(512, 1)
void k_gemm(const float* __restrict__ x,
            const float* __restrict__ a,
            const float* __restrict__ b) {
    extern __shared__ float sxf[];       // [16][SXF_STRIDE] = 65664 B; reused as red buf
    __shared__ u64 part[512];

    const int tid = threadIdx.x;
    const int bt  = blockIdx.x >> 2;
    const int kt  = blockIdx.x & 3;
    const int b0  = bt * 16;

    // ---- stage x: sxf[row*1026 + p] = x[b0+row][p]; 2 rows per pass ----
    {
        const int rhalf = tid >> 8;      // 0..1
        const int col4  = tid & 255;     // float4 column
        #pragma unroll
        for (int j = 0; j < 8; j++) {
            int row = j * 2 + rhalf;
            float4 v = ((const float4*)(x + (size_t)(b0 + row) * NP))[col4];
            float* dst = sxf + row * SXF_STRIDE + col4 * 4;
            ((float2*)dst)[0] = make_float2(v.x, v.y);
            ((float2*)dst)[1] = make_float2(v.z, v.w);
        }
    }
    __syncthreads();

    const int kq = tid & 3;
    const int rg = (tid >> 2) & 3;
    const int pg = tid >> 4;             // 0..31
    const int kcol  = kt * 4 + kq;       // ulonglong2 column (a/b row = 16 ull2)
    const int rbase = rg * 4;

    const ulonglong2* a2 = (const ulonglong2*)a;
    const ulonglong2* b2 = (const ulonglong2*)b;

    u64 acc[4][4];
    #pragma unroll
    for (int j = 0; j < 4; j++)
        #pragma unroll
        for (int c = 0; c < 4; c++) acc[j][c] = 0ull;

    #pragma unroll 4
    for (int p = pg; p < NP; p += 32) {
        ulonglong2 av = a2[p * 16 + kcol];
        ulonglong2 bv = b2[p * 16 + kcol];
        float v0 = sxf[(rbase + 0) * SXF_STRIDE + p];
        float v1 = sxf[(rbase + 1) * SXF_STRIDE + p];
        float v2 = sxf[(rbase + 2) * SXF_STRIDE + p];
        float v3 = sxf[(rbase + 3) * SXF_STRIDE + p];
        u64 x0 = pack2(v0, v0);
        u64 x1 = pack2(v1, v1);
        u64 x2 = pack2(v2, v2);
        u64 x3 = pack2(v3, v3);
        acc[0][0] = ffma2(x0, av.x, acc[0][0]);
        acc[0][1] = ffma2(x0, av.y, acc[0][1]);
        acc[0][2] = ffma2(x0, bv.x, acc[0][2]);
        acc[0][3] = ffma2(x0, bv.y, acc[0][3]);
        acc[1][0] = ffma2(x1, av.x, acc[1][0]);
        acc[1][1] = ffma2(x1, av.y, acc[1][1]);
        acc[1][2] = ffma2(x1, bv.x, acc[1][2]);
        acc[1][3] = ffma2(x1, bv.y, acc[1][3]);
        acc[2][0] = ffma2(x2, av.x, acc[2][0]);
        acc[2][1] = ffma2(x2, av.y, acc[2][1]);
        acc[2][2] = ffma2(x2, bv.x, acc[2][2]);
        acc[2][3] = ffma2(x2, bv.y, acc[2][3]);
        acc[3][0] = ffma2(x3, av.x, acc[3][0]);
        acc[3][1] = ffma2(x3, av.y, acc[3][1]);
        acc[3][2] = ffma2(x3, bv.x, acc[3][2]);
        acc[3][3] = ffma2(x3, bv.y, acc[3][3]);
    }

    __syncthreads();  // done reading sxf; reuse as reduction buffer

    // red[pg][local], local = r*16 + kq*4 + c  (r = row-in-tile 0..15) -> 256
    u64* red = (u64*)sxf;    // 32*256*8B = 64KB fits the 65.6KB buffer
    #pragma unroll
    for (int j = 0; j < 4; j++)
        #pragma unroll
        for (int c = 0; c < 4; c++)
            red[pg * 256 + (rbase + j) * 16 + kq * 4 + c] = acc[j][c];
    __syncthreads();

    // Each thread sums 16 of the 32 p-groups for one local entry.
    const int local = tid & 255;
    const int half  = tid >> 8;
    u64 v = red[(half * 16) * 256 + local];
    #pragma unroll
    for (int gg = 1; gg < 16; gg++)
        v = fadd2(v, red[(half * 16 + gg) * 256 + local]);
    part[tid] = v;
    __syncthreads();

    if (tid < 256) {
        u64 w = fadd2(part[tid], part[tid + 256]);
        const int r2  = tid >> 4;         // 0..15
        const int kq2 = (tid >> 2) & 3;
        const int c2  = tid & 3;
        float2 vv = unpack2(w);
        const int bb = b0 + r2;
        const int k0 = kt * 16 + kq2 * 4;
        if (c2 < 2) {
            *(float2*)&g_pa[bb * NK + k0 + 2 * c2] = vv;
        } else {
            *(float2*)&g_pb[bb * NK + k0 + 2 * (c2 - 2)] = vv;
        }
    }
}

// ============================================================================
// Kernel 2 (R14, frozen): out[b,p] = a0/(2P) + sum_k pa*cos(k th) + pb*sin.
// Sign-folded Chebyshev, two anchored chains (k=0, k=32), SPLIT accumulators,
// J=2, (256,4), grid = BATCH*2. Taylor for sin/cos(th); MUFU for 32*th.
// ============================================================================
__global__ __launch_bounds__(256, 4)
void k_fourier(const float* __restrict__ x,
               const float* __restrict__ a0,
               float* __restrict__ out) {
    __shared__ u64 s_e[NK];  // h_k * (pa_k, pb_k) packed

    const int b   = blockIdx.x >> 1;
    const int ph  = (blockIdx.x & 1) * 512;
    const int tid = threadIdx.x;

    if (tid < NK) {
        float pa = g_pa[b * NK + tid];
        float pb = g_pb[b * NK + tid];
        float sgn = ((tid >> 1) & 1) ? -1.0f : 1.0f;   // h_k = (-1)^floor(k/2)
        s_e[tid] = pack2(sgn * pa, sgn * pb);
    }
    __syncthreads();

    const float TWO_PI_OVER_P = 0.006135923151542565f;  // 2*pi/1024

    u64 eP[2], eC[2], fP[2], fC[2], sE[2], sF[2], P2[2], N2[2];
    u64 ce0 = s_e[0], ce1 = s_e[1], cf0 = s_e[32], cf1 = s_e[33];

    #pragma unroll
    for (int j = 0; j < 2; j++) {
        float xv = x[b * NP + ph + tid + 256 * j];
        float th = TWO_PI_OVER_P * xv;

        // sin/cos(th) via Taylor (|th| <= 0.04): ~1e-9 accurate, 6 FMA ops.
        float t  = th * th;
        float c1 = fmaf(t, fmaf(t, fmaf(t, -1.388888889e-3f, 4.166666667e-2f),
                                -0.5f), 1.0f);
        float s1 = th * fmaf(t, fmaf(t, 8.333333333e-3f, -1.666666667e-1f),
                             1.0f);

        float s32v, c32v;
        __sincosf(32.0f * th, &s32v, &c32v);

        float t2 = 2.0f * c1;
        P2[j] = pack2(t2, t2);
        N2[j] = pack2(-t2, -t2);

        eP[j] = pack2(1.0f, 0.0f);                 // g_0
        eC[j] = pack2(c1, s1);                     // g_1 (h_1 = +1)
        float c33 = fmaf(c32v, c1, -s32v * s1);
        float s33 = fmaf(s32v, c1,  c32v * s1);
        fP[j] = pack2(c32v, s32v);                 // f_0 (h_32 = +1)
        fC[j] = pack2(c33, s33);                   // f_1 (h_33 = +1)

        sE[j] = ffma2(ce0, eP[j], 0ull);
        sE[j] = ffma2(ce1, eC[j], sE[j]);
        sF[j] = ffma2(cf0, fP[j], 0ull);
        sF[j] = ffma2(cf1, fC[j], sF[j]);
    }

    #pragma unroll
    for (int i = 2; i < 32; i++) {
        u64 cE = s_e[i];
        u64 cF = s_e[32 + i];
        #pragma unroll
        for (int j = 0; j < 2; j++) {
            // g_i = (-1)^{i-1} * 2c1 * g_{i-1} + g_{i-2}
            u64 cst = (i & 1) ? P2[j] : N2[j];
            u64 en = ffma2(cst, eC[j], eP[j]);
            u64 fn = ffma2(cst, fC[j], fP[j]);
            sE[j] = ffma2(cE, en, sE[j]);
            sF[j] = ffma2(cF, fn, sF[j]);
            eP[j] = eC[j]; eC[j] = en;
            fP[j] = fC[j]; fC[j] = fn;
        }
    }

    float bias = a0[0] * (1.0f / (2.0f * (float)NP));
    #pragma unroll
    for (int j = 0; j < 2; j++) {
        float2 vE = unpack2(sE[j]);
        float2 vF = unpack2(sF[j]);
        out[b * NP + ph + tid + 256 * j] =
            (vE.x + vE.y) + (vF.x + vF.y) + bias;
    }
}

extern "C" void kernel_launch(void* const* d_in, const int* in_sizes, int n_in,
                              void* d_out, int out_size) {
    const float* x  = (const float*)d_in[0];
    const float* a  = (const float*)d_in[1];
    const float* b  = (const float*)d_in[2];
    const float* a0 = (const float*)d_in[3];
    float* out = (float*)d_out;

    // 16 rows x SXF_STRIDE floats = 65664 B dynamic smem (> 48KB default).
    cudaFuncSetAttribute(k_gemm, cudaFuncAttributeMaxDynamicSharedMemorySize,
                         16 * SXF_STRIDE * 4);

    k_gemm<<<128, 512, 16 * SXF_STRIDE * 4>>>(x, a, b);
    k_fourier<<<BATCH * 2, 256>>>(x, a0, out);
}

// round 16
// speedup vs baseline: 1.1347x; 1.1347x over previous
#include <cuda_runtime.h>

// Problem shape (fixed by dataset): x [512,1024] f32, a,b [1024,64,1] f32, a0 [1] f32
// out [512,1024] f32.
#define BATCH 512
#define NP    1024
#define NK    64

typedef unsigned long long u64;

// Scratch for the pa/pb GEMM results (device globals: allocation-free rule).
__device__ float g_pa[BATCH * NK];
__device__ float g_pb[BATCH * NK];

// ---------- packed f32x2 helpers (sm_103a FFMA2 path, PTX-only) ----------
__device__ __forceinline__ u64 ffma2(u64 a, u64 b, u64 c) {
    u64 d;
    asm("fma.rn.f32x2 %0, %1, %2, %3;" : "=l"(d) : "l"(a), "l"(b), "l"(c));
    return d;
}
__device__ __forceinline__ u64 fadd2(u64 a, u64 b) {
    u64 d;
    asm("add.rn.f32x2 %0, %1, %2;" : "=l"(d) : "l"(a), "l"(b));
    return d;
}
__device__ __forceinline__ u64 pack2(float lo, float hi) {
    u64 d;
    asm("mov.b64 %0, {%1, %2};"
        : "=l"(d) : "r"(__float_as_uint(lo)), "r"(__float_as_uint(hi)));
    return d;
}
__device__ __forceinline__ float2 unpack2(u64 v) {
    unsigned lo, hi;
    asm("mov.b64 {%0, %1}, %2;" : "=r"(lo), "=r"(hi) : "l"(v));
    return make_float2(__uint_as_float(lo), __uint_as_float(hi));
}

// ============================================================================
// Kernel 1 (R7, best of 6 tested variants): pa[b,k] = sum_p x[b,p]*a[p,k];
// pb likewise. Grid = 64 b-tiles (8 rows) x 4 k-tiles = 256 blocks,
// 256 threads, 3 CTA/SM (CTA multiplicity >> L2 traffic for this kernel).
// x staged as floats (32.9KB smem), packed to (x,x) u64 in-loop on the idle
// ALU pipe. Inner loop per p: 2x LDG.128 + 4x LDS.32 + 4x pack + 16 FFMA2.
// ============================================================================
#define SXF_STRIDE 1028   // floats; rows 4 apart hit distinct banks

__global__ __launch_bounds__(256, 3)
void k_gemm(const float* __restrict__ x,
            const float* __restrict__ a,
            const float* __restrict__ b) {
    extern __shared__ float sxf[];       // [8][SXF_STRIDE] = 32.9KB; reused as red buf
    __shared__ u64 part[256];

    const int tid = threadIdx.x;
    const int bt  = blockIdx.x >> 2;
    const int kt  = blockIdx.x & 3;
    const int b0  = bt * 8;

    {
        const int r = tid >> 5;
        const int l = tid & 31;
        const float4* xr = (const float4*)(x + (size_t)(b0 + r) * NP);
        float* dst = sxf + r * SXF_STRIDE;
        #pragma unroll
        for (int j = 0; j < 8; j++) {
            float4 v = xr[l + 32 * j];
            *(float4*)&dst[(l + 32 * j) * 4] = v;
        }
    }
    __syncthreads();

    const int kq = tid & 3;
    const int rg = (tid >> 2) & 1;
    const int pg = tid >> 3;
    const int kcol  = kt * 4 + kq;
    const int rbase = rg * 4;

    const ulonglong2* a2 = (const ulonglong2*)a;
    const ulonglong2* b2 = (const ulonglong2*)b;

    u64 acc[4][4];
    #pragma unroll
    for (int j = 0; j < 4; j++)
        #pragma unroll
        for (int c = 0; c < 4; c++) acc[j][c] = 0ull;

    #pragma unroll 4
    for (int p = pg; p < NP; p += 32) {
        ulonglong2 av = a2[p * 16 + kcol];
        ulonglong2 bv = b2[p * 16 + kcol];
        float v0 = sxf[(rbase + 0) * SXF_STRIDE + p];
        float v1 = sxf[(rbase + 1) * SXF_STRIDE + p];
        float v2 = sxf[(rbase + 2) * SXF_STRIDE + p];
        float v3 = sxf[(rbase + 3) * SXF_STRIDE + p];
        u64 x0 = pack2(v0, v0);
        u64 x1 = pack2(v1, v1);
        u64 x2 = pack2(v2, v2);
        u64 x3 = pack2(v3, v3);
        acc[0][0] = ffma2(x0, av.x, acc[0][0]);
        acc[0][1] = ffma2(x0, av.y, acc[0][1]);
        acc[0][2] = ffma2(x0, bv.x, acc[0][2]);
        acc[0][3] = ffma2(x0, bv.y, acc[0][3]);
        acc[1][0] = ffma2(x1, av.x, acc[1][0]);
        acc[1][1] = ffma2(x1, av.y, acc[1][1]);
        acc[1][2] = ffma2(x1, bv.x, acc[1][2]);
        acc[1][3] = ffma2(x1, bv.y, acc[1][3]);
        acc[2][0] = ffma2(x2, av.x, acc[2][0]);
        acc[2][1] = ffma2(x2, av.y, acc[2][1]);
        acc[2][2] = ffma2(x2, bv.x, acc[2][2]);
        acc[2][3] = ffma2(x2, bv.y, acc[2][3]);
        acc[3][0] = ffma2(x3, av.x, acc[3][0]);
        acc[3][1] = ffma2(x3, av.y, acc[3][1]);
        acc[3][2] = ffma2(x3, bv.x, acc[3][2]);
        acc[3][3] = ffma2(x3, bv.y, acc[3][3]);
    }

    __syncthreads();  // done reading sxf; reuse as reduction buffer

    u64* red = (u64*)sxf;
    #pragma unroll
    for (int j = 0; j < 4; j++)
        #pragma unroll
        for (int c = 0; c < 4; c++)
            red[pg * 128 + (rbase + j) * 16 + kq * 4 + c] = acc[j][c];
    __syncthreads();

    const int local = tid & 127;
    const int half  = tid >> 7;
    u64 v = red[(half * 16) * 128 + local];
    #pragma unroll
    for (int gg = 1; gg < 16; gg++)
        v = fadd2(v, red[(half * 16 + gg) * 128 + local]);
    part[tid] = v;
    __syncthreads();

    if (tid < 128) {
        u64 w = fadd2(part[tid], part[tid + 128]);
        const int r2  = tid >> 4;
        const int kq2 = (tid >> 2) & 3;
        const int c2  = tid & 3;
        float2 vv = unpack2(w);
        const int bb = b0 + r2;
        const int k0 = kt * 16 + kq2 * 4;
        if (c2 < 2) {
            *(float2*)&g_pa[bb * NK + k0 + 2 * c2] = vv;
        } else {
            *(float2*)&g_pb[bb * NK + k0 + 2 * (c2 - 2)] = vv;
        }
    }
}

// ============================================================================
// Kernel 2 (R5-exact, best of 8 tested variants): out[b,p] = a0/(2P)
//   + sum_k pa[b,k]*cos(k*th) + pb[b,k]*sin(k*th),  th = (2pi/P)*x[b,p].
// Sign-folded Chebyshev (h_k = (-1)^floor(k/2)):
//   g_{i+1} = (-1)^i * 2*c1 * g_i + g_{i-1}   (pure FFMA2, alternating const)
// Two chains anchored at k=0, k=32; MUFU __sincosf anchors (measured faster
// than the Taylor variant twice); SPLIT accumulators (1-deep chains);
// J=2 points/thread; __launch_bounds__(256,4); grid = BATCH*2.
// ============================================================================
__global__ __launch_bounds__(256, 4)
void k_fourier(const float* __restrict__ x,
               const float* __restrict__ a0,
               float* __restrict__ out) {
    __shared__ u64 s_e[NK];  // h_k * (pa_k, pb_k) packed

    const int b   = blockIdx.x >> 1;
    const int ph  = (blockIdx.x & 1) * 512;
    const int tid = threadIdx.x;

    if (tid < NK) {
        float pa = g_pa[b * NK + tid];
        float pb = g_pb[b * NK + tid];
        float sgn = ((tid >> 1) & 1) ? -1.0f : 1.0f;   // h_k = (-1)^floor(k/2)
        s_e[tid] = pack2(sgn * pa, sgn * pb);
    }
    __syncthreads();

    const float TWO_PI_OVER_P = 0.006135923151542565f;  // 2*pi/1024

    u64 eP[2], eC[2], fP[2], fC[2], sE[2], sF[2], P2[2], N2[2];
    u64 ce0 = s_e[0], ce1 = s_e[1], cf0 = s_e[32], cf1 = s_e[33];

    #pragma unroll
    for (int j = 0; j < 2; j++) {
        float xv = x[b * NP + ph + tid + 256 * j];
        float th = TWO_PI_OVER_P * xv;
        float s1, c1, s32v, c32v;
        __sincosf(th, &s1, &c1);
        __sincosf(32.0f * th, &s32v, &c32v);

        float t2 = 2.0f * c1;
        P2[j] = pack2(t2, t2);
        N2[j] = pack2(-t2, -t2);

        eP[j] = pack2(1.0f, 0.0f);                 // g_0
        eC[j] = pack2(c1, s1);                     // g_1 (h_1 = +1)
        float c33 = fmaf(c32v, c1, -s32v * s1);
        float s33 = fmaf(s32v, c1,  c32v * s1);
        fP[j] = pack2(c32v, s32v);                 // f_0 (h_32 = +1)
        fC[j] = pack2(c33, s33);                   // f_1 (h_33 = +1)

        sE[j] = ffma2(ce0, eP[j], 0ull);
        sE[j] = ffma2(ce1, eC[j], sE[j]);
        sF[j] = ffma2(cf0, fP[j], 0ull);
        sF[j] = ffma2(cf1, fC[j], sF[j]);
    }

    #pragma unroll
    for (int i = 2; i < 32; i++) {
        u64 cE = s_e[i];
        u64 cF = s_e[32 + i];
        #pragma unroll
        for (int j = 0; j < 2; j++) {
            // g_i = (-1)^{i-1} * 2c1 * g_{i-1} + g_{i-2}
            u64 cst = (i & 1) ? P2[j] : N2[j];
            u64 en = ffma2(cst, eC[j], eP[j]);
            u64 fn = ffma2(cst, fC[j], fP[j]);
            sE[j] = ffma2(cE, en, sE[j]);
            sF[j] = ffma2(cF, fn, sF[j]);
            eP[j] = eC[j]; eC[j] = en;
            fP[j] = fC[j]; fC[j] = fn;
        }
    }

    float bias = a0[0] * (1.0f / (2.0f * (float)NP));
    #pragma unroll
    for (int j = 0; j < 2; j++) {
        float2 vE = unpack2(sE[j]);
        float2 vF = unpack2(sF[j]);
        out[b * NP + ph + tid + 256 * j] =
            (vE.x + vE.y) + (vF.x + vF.y) + bias;
    }
}

extern "C" void kernel_launch(void* const* d_in, const int* in_sizes, int n_in,
                              void* d_out, int out_size) {
    const float* x  = (const float*)d_in[0];
    const float* a  = (const float*)d_in[1];
    const float* b  = (const float*)d_in[2];
    const float* a0 = (const float*)d_in[3];
    float* out = (float*)d_out;

    // 32896 B dynamic smem (< 48KB default; no attribute call needed).
    k_gemm<<<256, 256, 8 * SXF_STRIDE * 4>>>(x, a, b);
    k_fourier<<<BATCH * 2, 256>>>(x, a0, out);
}